// round 1
// baseline (speedup 1.0000x reference)
#include <cuda_runtime.h>

// Online Normalization forward.
// x: [B=32, H=64, W=64, C=256] channels-last, fp32.
// out[t] = (x[t] - mu_{t-1}) * rsqrt(var_{t-1} + eps), with the (mu, var)
// recurrence carried over the batch axis only through per-channel scalars.

#define AFWD 0.999f
#define EPS  1e-5f

constexpr int Bn    = 32;
constexpr int HW    = 64 * 64;          // 4096 spatial positions per batch
constexpr int Cc    = 256;
constexpr int S     = 16;               // spatial chunks for partial reduction
constexpr int CHUNK = HW / S;           // 256

// Scratch (static __device__ arrays: allocation-guard safe)
__device__ float g_psum[Bn * S * Cc];
__device__ float g_psq [Bn * S * Cc];
__device__ float g_mu  [Bn * Cc];       // mu_{t-1} per (t, c)
__device__ float g_rs  [Bn * Cc];       // rsqrt(var_{t-1}+eps) per (t, c)

// ---------------------------------------------------------------------------
// Pass 1: per-(batch, chunk, channel) partial sums. Coalesced: 256 threads
// span the channel dimension; each iteration the block reads 1024 contiguous B.
// ---------------------------------------------------------------------------
__global__ void stats_kernel(const float* __restrict__ x) {
    const int t  = blockIdx.x;
    const int ch = blockIdx.y;
    const int c  = threadIdx.x;
    const float* p = x + ((size_t)(t * HW + ch * CHUNK)) * Cc + c;
    float s = 0.f, s2 = 0.f;
    #pragma unroll 8
    for (int i = 0; i < CHUNK; i++) {
        float v = p[(size_t)i * Cc];
        s  += v;
        s2 = fmaf(v, v, s2);
    }
    const int idx = (t * S + ch) * Cc + c;
    g_psum[idx] = s;
    g_psq [idx] = s2;
}

// ---------------------------------------------------------------------------
// Pass 2: per-channel 32-step scan (tiny). One block, 256 threads = channels.
// Deterministic fixed-order reduction of the S partials, then the EMA update.
// ---------------------------------------------------------------------------
__global__ void scan_kernel(const float* __restrict__ mu0,
                            const float* __restrict__ var0) {
    const int c = threadIdx.x;
    float mu  = mu0[c];
    float var = var0[c];
    const float inv = 1.0f / (float)HW;
    for (int t = 0; t < Bn; t++) {
        g_mu[t * Cc + c] = mu;
        g_rs[t * Cc + c] = rsqrtf(var + EPS);
        float s = 0.f, s2 = 0.f;
        #pragma unroll
        for (int k = 0; k < S; k++) {
            s  += g_psum[(t * S + k) * Cc + c];
            s2 += g_psq [(t * S + k) * Cc + c];
        }
        const float mean = s * inv;
        const float vart = fmaf(-mean, mean, s2 * inv);   // E[x^2] - mean^2
        const float d    = mean - mu;
        var = AFWD * var + (1.0f - AFWD) * vart
            + AFWD * (1.0f - AFWD) * d * d;
        mu  = fmaf(1.0f - AFWD, d, mu);
    }
}

// ---------------------------------------------------------------------------
// Pass 3: normalize, float4-vectorized. Blocks mapped in REVERSE so the first
// wave reads the tail of x, which pass 1 just left resident in L2 (~126 MB).
// Each float4 covers 4 consecutive channels; mu/rscale broadcast from L2/L1.
// ---------------------------------------------------------------------------
__global__ void norm_kernel(const float4* __restrict__ x4,
                            float4* __restrict__ o4) {
    const unsigned rb = gridDim.x - 1u - blockIdx.x;
    const size_t g  = (size_t)rb * blockDim.x + threadIdx.x;
    const int c4 = (int)(g & 63u);          // C/4 = 64 float4 per position
    const int t  = (int)(g >> 18);          // HW * (C/4) = 4096*64 = 2^18
    const float4 v = x4[g];
    const float4 m = ((const float4*)g_mu)[t * 64 + c4];
    const float4 r = ((const float4*)g_rs)[t * 64 + c4];
    float4 o;
    o.x = (v.x - m.x) * r.x;
    o.y = (v.y - m.y) * r.y;
    o.z = (v.z - m.z) * r.z;
    o.w = (v.w - m.w) * r.w;
    o4[g] = o;
}

extern "C" void kernel_launch(void* const* d_in, const int* in_sizes, int n_in,
                              void* d_out, int out_size) {
    const float* x    = (const float*)d_in[0];
    const float* mu0  = (const float*)d_in[1];
    const float* var0 = (const float*)d_in[2];
    // d_in[3] = u0, d_in[4] = v0 — unused in the forward pass.
    float* out = (float*)d_out;

    stats_kernel<<<dim3(Bn, S), Cc>>>(x);
    scan_kernel<<<1, Cc>>>(mu0, var0);

    const size_t n4 = (size_t)Bn * HW * Cc / 4;   // 8,388,608 float4
    const int threads = 256;
    const int blocks  = (int)(n4 / threads);      // 32768
    norm_kernel<<<blocks, threads>>>((const float4*)x, (float4*)out);
}

// round 2
// speedup vs baseline: 1.6050x; 1.6050x over previous
#include <cuda_runtime.h>

// Online Normalization forward, fused persistent kernel.
// x: [B=32, H=64, W=64, C=256] channels-last, fp32.

#define AFWD 0.999f
#define EPS  1e-5f

constexpr int Bn    = 32;
constexpr int HW    = 64 * 64;     // 4096
constexpr int Cc    = 256;
constexpr int C4    = Cc / 4;      // 64 float4 per spatial position
constexpr int S     = 16;          // spatial chunks per batch
constexpr int CHUNK = HW / S;      // 256 rows per tile
constexpr int TILES = Bn * S;      // 512
constexpr int NCTA  = 128;         // 4 tiles per CTA, <= SM count, co-resident
constexpr int TPC   = TILES / NCTA;// 4

// Scratch
__device__ float g_psum[TILES * Cc];
__device__ float g_psq [TILES * Cc];
__device__ float g_tsum[Bn * Cc];
__device__ float g_tsq [Bn * Cc];
__device__ unsigned long long g_bar;   // monotonic across graph replays

// Dynamic smem layout (floats):
//   [0     : 8192)  mu per (t,c)
//   [8192  : 16384) rs per (t,c)
//   [16384 : 24576) tsum staging  (pass1: reduction sums at 16384, sqs at 20480)
//   [24576 : 32768) tsq  staging
constexpr int SMEM_FLOATS = 32768;     // 128 KB

__device__ __forceinline__ void grid_barrier() {
    __syncthreads();
    if (threadIdx.x == 0) {
        __threadfence();
        unsigned long long t = atomicAdd(&g_bar, 1ULL) + 1ULL;
        unsigned long long target = ((t + NCTA - 1ULL) / NCTA) * NCTA;
        while (*((volatile unsigned long long*)&g_bar) < target) { }
        __threadfence();
    }
    __syncthreads();
}

__global__ __launch_bounds__(1024, 1)
void onorm_fused(const float4* __restrict__ x4,
                 float4* __restrict__ o4,
                 const float* __restrict__ mu0,
                 const float* __restrict__ var0) {
    extern __shared__ float sm[];
    float* sm_mu = sm;
    float* sm_rs = sm + 8192;
    float* red_s = sm + 16384;        // 4096 floats (16 groups x 64 c4 x float4)
    float* red_q = sm + 20480;        // 4096 floats
    float* sm_ts = sm + 16384;        // stage-B staging (reuses red area)
    float* sm_tq = sm + 24576;

    const int tid = threadIdx.x;
    const int cta = blockIdx.x;
    const int c4  = tid & 63;         // float4 channel index
    const int g   = tid >> 6;         // 0..15 row group

    // ---------------- Pass 1: per-tile partial sums ----------------
    #pragma unroll
    for (int k = 0; k < TPC; k++) {
        const int tile = cta * TPC + k;
        const int t = tile >> 4, s = tile & 15;
        const size_t base = (size_t)(t * HW + s * CHUNK) * C4;
        const float4* p = x4 + base + (size_t)(g * 16) * C4 + c4;

        float4 a = {0.f,0.f,0.f,0.f}, q = {0.f,0.f,0.f,0.f};
        #pragma unroll 4
        for (int i = 0; i < 16; i++) {
            float4 v = p[(size_t)i * C4];
            a.x += v.x; a.y += v.y; a.z += v.z; a.w += v.w;
            q.x = fmaf(v.x, v.x, q.x); q.y = fmaf(v.y, v.y, q.y);
            q.z = fmaf(v.z, v.z, q.z); q.w = fmaf(v.w, v.w, q.w);
        }
        ((float4*)red_s)[g * 64 + c4] = a;
        ((float4*)red_q)[g * 64 + c4] = q;
        __syncthreads();
        if (tid < 64) {
            float4 sa = {0.f,0.f,0.f,0.f}, sq = {0.f,0.f,0.f,0.f};
            #pragma unroll
            for (int j = 0; j < 16; j++) {
                float4 va = ((float4*)red_s)[j * 64 + tid];
                float4 vq = ((float4*)red_q)[j * 64 + tid];
                sa.x += va.x; sa.y += va.y; sa.z += va.z; sa.w += va.w;
                sq.x += vq.x; sq.y += vq.y; sq.z += vq.z; sq.w += vq.w;
            }
            ((float4*)g_psum)[tile * 64 + tid] = sa;
            ((float4*)g_psq )[tile * 64 + tid] = sq;
        }
        __syncthreads();
    }

    grid_barrier();

    // ---------------- Stage A: reduce 16 partials -> per-(t,c) ----------------
    if (cta < Bn) {
        const int t = cta;
        // group g handles partial s=g (g in 0..15)
        float4 va = ((const float4*)g_psum)[(t * S + g) * 64 + c4];
        float4 vq = ((const float4*)g_psq )[(t * S + g) * 64 + c4];
        ((float4*)red_s)[g * 64 + c4] = va;
        ((float4*)red_q)[g * 64 + c4] = vq;
        __syncthreads();
        if (tid < 64) {
            float4 sa = {0.f,0.f,0.f,0.f}, sq = {0.f,0.f,0.f,0.f};
            #pragma unroll
            for (int j = 0; j < 16; j++) {
                float4 a = ((float4*)red_s)[j * 64 + tid];
                float4 q = ((float4*)red_q)[j * 64 + tid];
                sa.x += a.x; sa.y += a.y; sa.z += a.z; sa.w += a.w;
                sq.x += q.x; sq.y += q.y; sq.z += q.z; sq.w += q.w;
            }
            ((float4*)g_tsum)[t * 64 + tid] = sa;
            ((float4*)g_tsq )[t * 64 + tid] = sq;
        }
    } else {
        __syncthreads();  // keep barrier participation symmetric
    }

    grid_barrier();

    // ---------------- Stage B: redundant per-CTA scan into smem ----------------
    // Cooperative parallel load of all 8192 (t,c) sums into smem, then scan.
    #pragma unroll
    for (int i = tid; i < Bn * Cc; i += 1024) {
        sm_ts[i] = g_tsum[i];
        sm_tq[i] = g_tsq [i];
    }
    __syncthreads();
    if (tid < Cc) {
        const int c = tid;
        float mu  = mu0[c];
        float var = var0[c];
        const float inv = 1.0f / (float)HW;
        #pragma unroll
        for (int t = 0; t < Bn; t++) {
            sm_mu[t * Cc + c] = mu;
            sm_rs[t * Cc + c] = rsqrtf(var + EPS);
            const float mean = sm_ts[t * Cc + c] * inv;
            const float vart = fmaf(-mean, mean, sm_tq[t * Cc + c] * inv);
            const float d    = mean - mu;
            var = AFWD * var + (1.0f - AFWD) * vart
                + AFWD * (1.0f - AFWD) * d * d;
            mu  = fmaf(1.0f - AFWD, d, mu);
        }
    }
    __syncthreads();

    // ---------------- Pass 3: normalize (reverse tile order for L2 reuse) -----
    #pragma unroll
    for (int k = TPC - 1; k >= 0; k--) {
        const int tile = cta * TPC + k;
        const int t = tile >> 4, s = tile & 15;
        const size_t base = (size_t)(t * HW + s * CHUNK) * C4;
        const float4 m = ((const float4*)sm_mu)[t * 64 + c4];
        const float4 r = ((const float4*)sm_rs)[t * 64 + c4];
        const float4* p = x4 + base + (size_t)(g * 16) * C4 + c4;
        float4*       o = o4 + base + (size_t)(g * 16) * C4 + c4;
        #pragma unroll 4
        for (int i = 15; i >= 0; i--) {
            float4 v = p[(size_t)i * C4];
            float4 w;
            w.x = (v.x - m.x) * r.x;
            w.y = (v.y - m.y) * r.y;
            w.z = (v.z - m.z) * r.z;
            w.w = (v.w - m.w) * r.w;
            o[(size_t)i * C4] = w;
        }
    }
}

extern "C" void kernel_launch(void* const* d_in, const int* in_sizes, int n_in,
                              void* d_out, int out_size) {
    const float* x    = (const float*)d_in[0];
    const float* mu0  = (const float*)d_in[1];
    const float* var0 = (const float*)d_in[2];
    float* out = (float*)d_out;

    static bool attr_set = false;
    if (!attr_set) {
        cudaFuncSetAttribute(onorm_fused,
                             cudaFuncAttributeMaxDynamicSharedMemorySize,
                             SMEM_FLOATS * sizeof(float));
        attr_set = true;
    }

    onorm_fused<<<NCTA, 1024, SMEM_FLOATS * sizeof(float)>>>(
        (const float4*)x, (float4*)out, mu0, var0);
}